// round 1
// baseline (speedup 1.0000x reference)
#include <cuda_runtime.h>
#include <math.h>

#define NTRAJ 512
#define NTP 64
#define NSTEP 63
#define NIN 512
#define NLAT 1024
#define NUNITS 100
#define NCLUS 256
#define DCAT 1536

// ---------------- scratch (device globals: no runtime allocation) ----------
__device__ float g_h[NTRAJ * NLAT];      // recurrent state
__device__ float g_u[NTRAJ * NLAT];      // update gate
__device__ float g_hr[NTRAJ * NLAT];     // h * r
__device__ float g_t1p[4 * NTRAJ * NUNITS];  // K-split partials of h@W1
__device__ float g_lp[4 * NTRAJ * NCLUS];    // K-split partials of h@We

enum { ASRC_PLAIN = 0, ASRC_CONCAT = 1, ASRC_TANH = 2 };
enum { EPI_GATES = 0, EPI_NEWH = 1, EPI_EULER = 2, EPI_LOGITS = 3 };

#define BM 64
#define BN 64
#define BK 16

// Generic 64x64 tiled fp32 GEMM, 128 threads, 8x4 outputs per thread.
// A source and epilogue selected at compile time.
template <int ASRC, int EPI>
__global__ void __launch_bounds__(128) gemm_k(
    const float* __restrict__ A, const float* __restrict__ Ad, int lda,
    const float* __restrict__ B0, const float* __restrict__ B1, int ldb,
    int K, int KS,
    const float* __restrict__ bias0, const float* __restrict__ bias1,
    const float* __restrict__ ts, const float* __restrict__ uin,
    float* __restrict__ hbuf, float* __restrict__ out0, float* __restrict__ out1,
    int t)
{
    __shared__ float As[BK][68];   // padded: avoids 16-way store conflicts, keeps 16B align
    __shared__ float Bs[BK][BN];

    const int tid = threadIdx.x;
    const int tx = tid & 15;       // 16 col groups * 4 cols
    const int ty = tid >> 4;       // 8 row groups * 8 rows
    const int r0 = blockIdx.x * BM;
    const int c0 = blockIdx.y * BN;

    const float* Bp = B0;
    int cb = c0;
    if (EPI == EPI_GATES) {                 // N=2048: left half = W_u, right = W_r
        if (c0 >= NLAT) { Bp = B1; cb = c0 - NLAT; }
    }

    float acc[8][4];
#pragma unroll
    for (int i = 0; i < 8; i++)
#pragma unroll
        for (int j = 0; j < 4; j++) acc[i][j] = 0.f;

    const int k0 = blockIdx.z * KS;
    const int k1 = (k0 + KS < K) ? (k0 + KS) : K;

    for (int kk = k0; kk < k1; kk += BK) {
        // ---- load A tile (transposed into shared) ----
#pragma unroll
        for (int i = 0; i < 8; i++) {
            int idx = tid + i * 128;
            int m = idx >> 4, kq = idx & 15;
            int gk = kk + kq;
            float v = 0.f;
            if (ASRC == ASRC_PLAIN) {
                if (gk < k1) v = A[(r0 + m) * lda + gk];
            } else if (ASRC == ASRC_CONCAT) {
                // A = [state(512x1024) | data[:, t, :](512x512)]
                if (gk < NLAT) v = A[(r0 + m) * NLAT + gk];
                else           v = Ad[(r0 + m) * (NTP * NIN) + t * NIN + (gk - NLAT)];
            } else { // ASRC_TANH: A = tanh(b1 + sum of 4 K-split partials)
                if (gk < k1) {
                    int row = r0 + m;
                    float s = bias1[gk];
                    s += A[0 * (NTRAJ * NUNITS) + row * NUNITS + gk];
                    s += A[1 * (NTRAJ * NUNITS) + row * NUNITS + gk];
                    s += A[2 * (NTRAJ * NUNITS) + row * NUNITS + gk];
                    s += A[3 * (NTRAJ * NUNITS) + row * NUNITS + gk];
                    v = tanhf(s);
                }
            }
            As[kq][m] = v;
        }
        // ---- load B tile ----
#pragma unroll
        for (int i = 0; i < 8; i++) {
            int idx = tid + i * 128;
            int kq = idx >> 6, n = idx & 63;
            int gk = kk + kq;
            Bs[kq][n] = (gk < k1) ? Bp[gk * ldb + cb + n] : 0.f;
        }
        __syncthreads();
        // ---- FMA ----
#pragma unroll
        for (int k = 0; k < BK; k++) {
            float4 a0 = *(const float4*)&As[k][ty * 8];
            float4 a1 = *(const float4*)&As[k][ty * 8 + 4];
            float4 b  = *(const float4*)&Bs[k][tx * 4];
            float av[8] = {a0.x, a0.y, a0.z, a0.w, a1.x, a1.y, a1.z, a1.w};
            float bv[4] = {b.x, b.y, b.z, b.w};
#pragma unroll
            for (int i = 0; i < 8; i++)
#pragma unroll
                for (int j = 0; j < 4; j++)
                    acc[i][j] += av[i] * bv[j];
        }
        __syncthreads();
    }

    // ---- epilogue ----
#pragma unroll
    for (int i = 0; i < 8; i++) {
        int row = r0 + ty * 8 + i;
#pragma unroll
        for (int j = 0; j < 4; j++) {
            int col = c0 + tx * 4 + j;
            float v = acc[i][j];
            if (EPI == EPI_GATES) {
                float b = (col < NLAT) ? bias0[col] : bias1[col - NLAT];
                float s = 1.f / (1.f + expf(-(v + b)));
                if (col < NLAT) {
                    out0[row * NLAT + col] = s;                 // u gate
                } else {
                    int c = col - NLAT;
                    out1[row * NLAT + c] = hbuf[row * NLAT + c] * s;  // h*r
                }
            } else if (EPI == EPI_NEWH) {
                float n  = v + bias0[col];
                float uu = uin[row * NLAT + col];
                float ho = hbuf[row * NLAT + col];
                hbuf[row * NLAT + col] = (1.f - uu) * n + uu * ho;    // GRU blend
            } else if (EPI == EPI_EULER) {
                float sub = 0.5f * (ts[t + 1] - ts[t]);               // dt / (N_INTER-1)
                hbuf[row * NLAT + col] += sub * (v + bias0[col]);
            } else { // EPI_LOGITS: write K-split partial (bias added in softmax)
                out0[blockIdx.z * (NTRAJ * NCLUS) + row * NCLUS + col] = v;
            }
        }
    }
}

// h@W1 partial GEMM: grid (32 row-blocks of 16, 4 K-splits of 256). N=100.
__global__ void __launch_bounds__(256) ode1_k(const float* __restrict__ h,
                                              const float* __restrict__ W1,
                                              float* __restrict__ t1p)
{
    __shared__ float As[16][17];
    __shared__ float Ws[16][100];
    const int tx = threadIdx.x;              // 0..127 (col; active < 100)
    const int ty = threadIdx.y;              // 0..1
    const int tid = ty * 128 + tx;
    const int r0 = blockIdx.x * 16;
    const int ks = blockIdx.y;
    float acc[8];
#pragma unroll
    for (int i = 0; i < 8; i++) acc[i] = 0.f;

    for (int kk = ks * 256; kk < ks * 256 + 256; kk += 16) {
        {
            int m = tid >> 4, kq = tid & 15;
            As[kq][m] = h[(r0 + m) * NLAT + kk + kq];
        }
        for (int idx = tid; idx < 1600; idx += 256) {
            int kq = idx / 100, c = idx - kq * 100;
            Ws[kq][c] = W1[(kk + kq) * NUNITS + c];
        }
        __syncthreads();
        if (tx < 100) {
#pragma unroll
            for (int kq = 0; kq < 16; kq++) {
                float w = Ws[kq][tx];
#pragma unroll
                for (int rr = 0; rr < 8; rr++)
                    acc[rr] += As[kq][ty * 8 + rr] * w;
            }
        }
        __syncthreads();
    }
    if (tx < 100) {
#pragma unroll
        for (int rr = 0; rr < 8; rr++)
            t1p[ks * (NTRAJ * NUNITS) + (r0 + ty * 8 + rr) * NUNITS + tx] = acc[rr];
    }
}

// Sum logits partials + bias, softmax over 256 clusters, and copy states out.
__global__ void __launch_bounds__(256) softmax_states_k(
    const float* __restrict__ lp, const float* __restrict__ be,
    const float* __restrict__ h,
    float* __restrict__ prob_out, float* __restrict__ state_out)
{
    const int row = blockIdx.x;
    const int tid = threadIdx.x;
    __shared__ float smax[8], ssum[8];

    float v = be[tid];
#pragma unroll
    for (int s = 0; s < 4; s++) v += lp[s * (NTRAJ * NCLUS) + row * NCLUS + tid];

    float m = v;
#pragma unroll
    for (int o = 16; o > 0; o >>= 1) m = fmaxf(m, __shfl_xor_sync(0xffffffffu, m, o));
    if ((tid & 31) == 0) smax[tid >> 5] = m;
    __syncthreads();
    float mx = smax[0];
#pragma unroll
    for (int w = 1; w < 8; w++) mx = fmaxf(mx, smax[w]);

    float e = expf(v - mx);
    float s = e;
#pragma unroll
    for (int o = 16; o > 0; o >>= 1) s += __shfl_xor_sync(0xffffffffu, s, o);
    if ((tid & 31) == 0) ssum[tid >> 5] = s;
    __syncthreads();
    float tot = 0.f;
#pragma unroll
    for (int w = 0; w < 8; w++) tot += ssum[w];

    prob_out[row * NCLUS + tid] = e / tot;
#pragma unroll
    for (int i = 0; i < 4; i++)
        state_out[row * NLAT + i * 256 + tid] = h[row * NLAT + i * 256 + tid];
}

__global__ void zero_k(float* __restrict__ p, int n)
{
    int i = blockIdx.x * blockDim.x + threadIdx.x;
    if (i < n) p[i] = 0.f;
}

extern "C" void kernel_launch(void* const* d_in, const int* in_sizes, int n_in,
                              void* d_out, int out_size)
{
    const float* data = (const float*)d_in[0];
    const float* ts   = (const float*)d_in[1];
    const float* W_u  = (const float*)d_in[2];
    const float* b_u  = (const float*)d_in[3];
    const float* W_r  = (const float*)d_in[4];
    const float* b_r  = (const float*)d_in[5];
    const float* W_n  = (const float*)d_in[6];
    const float* b_n  = (const float*)d_in[7];
    const float* W1   = (const float*)d_in[8];
    const float* b1   = (const float*)d_in[9];
    const float* W2   = (const float*)d_in[10];
    const float* b2   = (const float*)d_in[11];
    const float* We   = (const float*)d_in[12];
    const float* be   = (const float*)d_in[13];
    float* out = (float*)d_out;

    float *h, *u, *hr, *t1p, *lp;
    cudaGetSymbolAddress((void**)&h, g_h);
    cudaGetSymbolAddress((void**)&u, g_u);
    cudaGetSymbolAddress((void**)&hr, g_hr);
    cudaGetSymbolAddress((void**)&t1p, g_t1p);
    cudaGetSymbolAddress((void**)&lp, g_lp);

    zero_k<<<(NTRAJ * NLAT + 255) / 256, 256>>>(h, NTRAJ * NLAT);

    float* probs  = out;
    float* states = out + (size_t)NSTEP * NTRAJ * NCLUS;

    for (int t = 0; t < NSTEP; t++) {
        // u,r gates: [h|x] @ [W_u | W_r], sigmoid; emits u and h*r
        gemm_k<ASRC_CONCAT, EPI_GATES><<<dim3(8, 32, 1), 128>>>(
            h, data, NLAT, W_u, W_r, NLAT, DCAT, DCAT,
            b_u, b_r, nullptr, nullptr, h, u, hr, t);
        // n gate + GRU blend: h = (1-u)*([h*r|x] @ W_n + b_n) + u*h
        gemm_k<ASRC_CONCAT, EPI_NEWH><<<dim3(8, 16, 1), 128>>>(
            hr, data, NLAT, W_n, nullptr, NLAT, DCAT, DCAT,
            b_n, nullptr, nullptr, u, h, nullptr, nullptr, t);
        // 2 Euler steps: h += sub * (tanh(h@W1+b1) @ W2 + b2)
        for (int e = 0; e < 2; e++) {
            ode1_k<<<dim3(32, 4), dim3(128, 2)>>>(h, W1, t1p);
            gemm_k<ASRC_TANH, EPI_EULER><<<dim3(8, 16, 1), 128>>>(
                t1p, nullptr, 0, W2, nullptr, NLAT, NUNITS, NUNITS,
                b2, b1, ts, nullptr, h, nullptr, nullptr, t);
        }
        // emission logits (K split by 4 for parallelism), then softmax + state copy
        gemm_k<ASRC_PLAIN, EPI_LOGITS><<<dim3(8, 4, 4), 128>>>(
            h, nullptr, NLAT, We, nullptr, NCLUS, NLAT, 256,
            nullptr, nullptr, nullptr, nullptr, nullptr, lp, nullptr, t);
        softmax_states_k<<<NTRAJ, 256>>>(lp, be, h,
            probs  + (size_t)t * NTRAJ * NCLUS,
            states + (size_t)t * NTRAJ * NLAT);
    }
}